// round 9
// baseline (speedup 1.0000x reference)
#include <cuda_runtime.h>
#include <math.h>

#define NC      16
#define NBINS   4096            // 16^3 distinct (a,p,n) triplets
#define MARGIN_F 0.3f
#define EPS_F    1e-8f
#define NDIST   256             // one block per (i,j) pair
#define NHIST   256             // histogram blocks
#define NTHR    256
#define GRID    (1 + NDIST + NHIST)

// ---------------- device-global scratch (no allocations allowed) -----------
// Zero-initialized at load; final block resets everything each run so every
// graph replay starts clean.
__device__ int   g_hist[NBINS];
__device__ float g_D16[NC * NC];
__device__ int   g_dist_cnt = 0;
__device__ int   g_hist_cnt = 0;

__device__ __forceinline__ float ldcg_f(const float* p) {
    float v; asm volatile("ld.global.cg.f32 %0, [%1];" : "=f"(v) : "l"(p)); return v;
}
__device__ __forceinline__ int ldcg_i(const int* p) {
    int v; asm volatile("ld.global.cg.s32 %0, [%1];" : "=r"(v) : "l"(p)); return v;
}

__global__ void __launch_bounds__(NTHR) k_fused(
    const float* __restrict__ x,        // inputs [B, D]
    const int*   __restrict__ targets,  // targets_mat [B] (int32: JAX downcast)
    const int*   __restrict__ ua,       // user_answers [T,3] (int32)
    float*       __restrict__ out,
    int B, int D, int T, int out_n)
{
    __shared__ int   s_first[NC];
    __shared__ int   s_flag;
    __shared__ float sD[NC * NC];
    __shared__ float sr0[NTHR / 32], sr1[NTHR / 32], sr2[NTHR / 32];
    __shared__ double dr[NTHR / 32], dp2[NTHR / 32];
    __shared__ unsigned long long dc[NTHR / 32];

    const int tid = threadIdx.x;
    const int bid = blockIdx.x;

    // ================= HIST BLOCKS: bids [1+NDIST, 1+NDIST+NHIST) ==========
    // No dependency on anything: histogram the triplet classes and exit.
    if (bid >= 1 + NDIST) {
        int hid = bid - 1 - NDIST;
        for (int t = hid * NTHR + tid; t < T; t += NHIST * NTHR) {
            int a = ua[3 * t + 0];
            int p = ua[3 * t + 1];
            int n = ua[3 * t + 2];
            if ((unsigned)a < NC && (unsigned)p < NC && (unsigned)n < NC) {
                int bin = (a << 8) | (p << 4) | n;
                atomicAdd(&g_hist[bin], 1);     // result unused -> REDG
            }
        }
        __threadfence();
        __syncthreads();
        if (tid == 0) atomicAdd(&g_hist_cnt, 1);
        return;
    }

    // ---- shared scan with early exit (dist blocks and final block) --------
    // first-occurrence index per class; chunks processed in index order, so
    // once all 16 classes are found later chunks cannot lower any minimum.
    if (tid < NC) s_first[tid] = B;             // sentinel = absent
    __syncthreads();
    for (int base = 0; base < B; base += NTHR) {
        int i = base + tid;
        if (i < B) {
            unsigned c = (unsigned)targets[i];
            if (c < NC && i < s_first[c]) atomicMin(&s_first[c], i);
        }
        __syncthreads();
        if (tid == 0) {
            int nf = 0;
#pragma unroll
            for (int k = 0; k < NC; k++) nf += (s_first[k] < B) ? 1 : 0;
            s_flag = (nf == NC) ? 1 : 0;
        }
        __syncthreads();
        if (s_flag) break;
    }

    // ================= DIST BLOCKS: bids [1, 1+NDIST) ======================
    if (bid >= 1) {
        int pair = bid - 1;
        int i = pair >> 4, j = pair & 15;
        int fi = s_first[i]; if (fi >= B) fi = 0;   // argmax-over-all-false == 0
        int fj = s_first[j]; if (fj >= B) fj = 0;
        const float* xi = x + (size_t)fi * (size_t)D;
        const float* xj = x + (size_t)fj * (size_t)D;

        float sii = 0.f, sjj = 0.f, sij = 0.f;
        int nv4 = D >> 2;
        const float4* xi4 = (const float4*)xi;
        const float4* xj4 = (const float4*)xj;
        for (int k = tid; k < nv4; k += NTHR) {
            float4 a = xi4[k];
            float4 b = xj4[k];
            sii += a.x * a.x + a.y * a.y + a.z * a.z + a.w * a.w;
            sjj += b.x * b.x + b.y * b.y + b.z * b.z + b.w * b.w;
            sij += a.x * b.x + a.y * b.y + a.z * b.z + a.w * b.w;
        }
        for (int k = (nv4 << 2) + tid; k < D; k += NTHR) {  // tail (D%4)
            float a = xi[k], b = xj[k];
            sii += a * a; sjj += b * b; sij += a * b;
        }
        for (int off = 16; off > 0; off >>= 1) {
            sii += __shfl_down_sync(0xFFFFFFFFu, sii, off);
            sjj += __shfl_down_sync(0xFFFFFFFFu, sjj, off);
            sij += __shfl_down_sync(0xFFFFFFFFu, sij, off);
        }
        int w = tid >> 5, l = tid & 31;
        if (l == 0) { sr0[w] = sii; sr1[w] = sjj; sr2[w] = sij; }
        __syncthreads();
        if (tid == 0) {
            float a = 0.f, b = 0.f, c = 0.f;
            for (int w2 = 0; w2 < NTHR / 32; w2++) { a += sr0[w2]; b += sr1[w2]; c += sr2[w2]; }
            float d2 = fmaxf(a + b - 2.0f * c, 1e-12f);
            g_D16[pair] = sqrtf(d2);
            __threadfence();
            atomicAdd(&g_dist_cnt, 1);
        }
        return;
    }

    // ================= FINAL BLOCK: bid 0 ==================================
    // Wait for all dist + hist blocks (plain-load spin; all blocks of this
    // grid are co-resident: 513 blocks <= 4/SM by regs/smem/warps).
    if (tid == 0) {
        volatile int* vd = &g_dist_cnt;
        volatile int* vh = &g_hist_cnt;
        while (*vd < NDIST || *vh < NHIST) { __nanosleep(64); }
    }
    __syncthreads();
    __threadfence();
    if (tid < NC * NC) sD[tid] = ldcg_f(&g_D16[tid]);   // bypass stale L1
    __syncthreads();

    // Evaluate the 4096 bins (16 per thread), weight by histogram count.
    double rsum = 0.0, psum = 0.0;
    unsigned long long cnt = 0;
    for (int b = tid; b < NBINS; b += NTHR) {
        int h = ldcg_i(&g_hist[b]);
        g_hist[b] = 0;                                  // reset for next replay
        if (h > 0) {
            int a = b >> 8, p = (b >> 4) & 15, n = b & 15;
            if (s_first[a] < B && s_first[p] < B && s_first[n] < B) {
                float dap = sD[(a << 4) | p];
                float dan = sD[(a << 4) | n];
                float rank = fmaxf(dap - dan + MARGIN_F, 0.0f);
                float sap = 1.0f / (dap + 1.0f);
                float san = 1.0f / (dan + 1.0f);
                float per = -logf(sap / (sap + san) + EPS_F);
                rsum += (double)h * (double)rank;
                psum += (double)h * (double)per;
                cnt  += (unsigned long long)h;
            }
        }
    }
    for (int off = 16; off > 0; off >>= 1) {
        rsum += __shfl_down_sync(0xFFFFFFFFu, rsum, off);
        psum += __shfl_down_sync(0xFFFFFFFFu, psum, off);
        cnt  += __shfl_down_sync(0xFFFFFFFFu, cnt,  off);
    }
    {
        int w = tid >> 5, l = tid & 31;
        if (l == 0) { dr[w] = rsum; dp2[w] = psum; dc[w] = cnt; }
    }
    __syncthreads();
    if (tid == 0) {
        double R = 0.0, P = 0.0;
        unsigned long long C = 0;
        for (int w2 = 0; w2 < NTHR / 32; w2++) { R += dr[w2]; P += dp2[w2]; C += dc[w2]; }
        double nv = (double)C;
        if (nv < 1.0) nv = 1.0;
        float lh = (float)(R / nv);
        float lp = (float)(P / nv);
        if (out_n > 0) out[0] = lh + lp;                // W_HUMAN = W_PER = 1
        if (out_n > 1) out[1] = lh;
        if (out_n > 2) out[2] = lp;
        g_dist_cnt = 0;                                 // reset for next replay
        g_hist_cnt = 0;
        __threadfence();
    }
}

// ---------------- launch ----------------------------------------------------
// Inputs identified BY SIZE (robust to metadata ordering):
//   inputs       : largest element count              (4096*1024 = 4194304)
//   user_answers : only remaining size divisible by 3 (100000*3  = 300000)
//   targets_mat  : FIRST entry with the minimum size  (4096; targets_sub is
//                  the second 4096 entry, dict order preserved)
extern "C" void kernel_launch(void* const* d_in, const int* in_sizes, int n_in,
                              void* d_out, int out_size) {
    int idx_inputs = -1, idx_ua = -1, idx_tm = -1;
    int max_sz = -1;
    for (int i = 0; i < n_in; i++)
        if (in_sizes[i] > max_sz) { max_sz = in_sizes[i]; idx_inputs = i; }
    for (int i = 0; i < n_in; i++) {
        if (i == idx_inputs) continue;
        if ((in_sizes[i] % 3) == 0) { idx_ua = i; break; }
    }
    int min_sz = 0x7fffffff;
    for (int i = 0; i < n_in; i++) {
        if (i == idx_inputs || i == idx_ua) continue;
        if (in_sizes[i] < min_sz) min_sz = in_sizes[i];
    }
    for (int i = 0; i < n_in; i++) {
        if (i == idx_inputs || i == idx_ua) continue;
        if (in_sizes[i] == min_sz) { idx_tm = i; break; }   // first occurrence
    }
    if (idx_inputs < 0 || idx_ua < 0 || idx_tm < 0) return;

    const float* inputs   = (const float*)d_in[idx_inputs];
    const int*   targets  = (const int*)d_in[idx_tm];
    const int*   user_ans = (const int*)d_in[idx_ua];
    float* out = (float*)d_out;

    int B = in_sizes[idx_tm];
    int D = in_sizes[idx_inputs] / B;
    int T = in_sizes[idx_ua] / 3;

    k_fused<<<GRID, NTHR>>>(inputs, targets, user_ans, out, B, D, T, out_size);
}